// round 1
// baseline (speedup 1.0000x reference)
#include <cuda_runtime.h>

// Fused NodeAttention + single-head GAT layer.
// Shapes: B=65536, M=8, F_IN=F_OUT=128. All fp32.
//
// Per batch b:
//   e_n[m]      = h[b,m,:] . a_node
//   attn_n      = softmax_m(leaky_relu(e_n, 0.2))
//   wh[m,f]     = h[b,m,f] * (1 + attn_n[m])
//   Wh[m,o]     = sum_f wh[m,f] * W[f,o]
//   Wh1[m]      = Wh[m,:] . a[0:128] ;  Wh2[m] = Wh[m,:] . a[128:256]
//   e[i,j]      = Wh1[j] + Wh2[i]   (masked by adj>0 with -9e15)
//   att         = softmax_j(e)
//   out[b,i,o]  = relu(sum_j att[i,j] * Wh[j,o])
//
// Block = 256 threads (8 warps), NB=8 batches per block.
// W (64KB) staged in dynamic smem once per block (repeat reads hit L2).
// GEMM mapping: warp == m, lane owns 4 consecutive o -> inner loop is
// 1 broadcast LDS + 1 LDS.128 + 4 FFMA (fma-pipe bound, not smem bound).

#define MM 8
#define FF 128
#define ALPHA 0.2f
#define NEGV  (-9e15f)
#define NB 8
#define THREADS 256

// smem layout (floats)
#define OFF_WS     0
#define OFF_ANODE  (OFF_WS + FF * FF)          // 16384
#define OFF_A1     (OFF_ANODE + FF)            // 16512
#define OFF_A2     (OFF_A1 + FF)               // 16640
#define OFF_HS     (OFF_A2 + FF)               // 16768
#define OFF_WHS    (OFF_HS + MM * FF)          // 17792
#define OFF_ADJ    (OFF_WHS + MM * FF)         // 18816
#define OFF_EN     (OFF_ADJ + MM * MM)         // 18880
#define OFF_WH1    (OFF_EN + MM)               // 18888
#define OFF_WH2    (OFF_WH1 + MM)              // 18896
#define OFF_ATT    (OFF_WH2 + MM)              // 18904
#define SMEM_FLOATS (OFF_ATT + MM * MM)        // 18968 -> 75872 bytes

__global__ __launch_bounds__(THREADS) void gat_fused_kernel(
    const float* __restrict__ h,
    const float* __restrict__ adj,
    const float* __restrict__ W,
    const float* __restrict__ a,
    const float* __restrict__ a_node,
    float* __restrict__ out,
    int B)
{
    extern __shared__ float smem[];
    float* Ws      = smem + OFF_WS;
    float* a_nodeS = smem + OFF_ANODE;
    float* a1S     = smem + OFF_A1;
    float* a2S     = smem + OFF_A2;
    float* hs      = smem + OFF_HS;
    float* Whs     = smem + OFF_WHS;
    float* adjS    = smem + OFF_ADJ;
    float* enS     = smem + OFF_EN;
    float* wh1S    = smem + OFF_WH1;
    float* wh2S    = smem + OFF_WH2;
    float* attS    = smem + OFF_ATT;

    const int t    = threadIdx.x;
    const int lane = t & 31;
    const int warp = t >> 5;   // warp == m-row

    // ---- block prologue: stage W, a_node, a1, a2 ----
    for (int i = t * 4; i < FF * FF; i += THREADS * 4) {
        *(float4*)(Ws + i) = *(const float4*)(W + i);
    }
    if (t < FF) {
        a_nodeS[t] = a_node[t];
        a1S[t]     = a[t];
        a2S[t]     = a[FF + t];
    }
    __syncthreads();

    const int b0 = blockIdx.x * NB;

    for (int bi = 0; bi < NB; ++bi) {
        const int b = b0 + bi;
        if (b >= B) break;

        // ---- stage a: load h tile (8x128) + adj (8x8) ----
        {
            const float4 hv = *((const float4*)(h + (size_t)b * (MM * FF)) + t);
            *(float4*)(hs + t * 4) = hv;
            if (t < MM * MM) adjS[t] = adj[(size_t)b * (MM * MM) + t];
        }
        __syncthreads();

        // ---- stage b: e_n[m] = h[m,:] . a_node  (warp m) ----
        {
            float4 hr = *(const float4*)(hs + warp * FF + lane * 4);
            float4 av = *(const float4*)(a_nodeS + lane * 4);
            float p = hr.x * av.x + hr.y * av.y + hr.z * av.z + hr.w * av.w;
            #pragma unroll
            for (int d = 16; d; d >>= 1) p += __shfl_xor_sync(0xffffffffu, p, d);
            if (lane == 0) enS[warp] = p;
        }
        __syncthreads();

        // ---- stage c: node softmax (redundant per-thread) + scale own 4 elems ----
        {
            float lr[MM];
            float mx = -3.0e38f;
            #pragma unroll
            for (int m = 0; m < MM; ++m) {
                float v = enS[m];
                v = (v > 0.0f) ? v : ALPHA * v;
                lr[m] = v;
                mx = fmaxf(mx, v);
            }
            float sum = 0.0f;
            #pragma unroll
            for (int m = 0; m < MM; ++m) { lr[m] = expf(lr[m] - mx); sum += lr[m]; }
            const float s = 1.0f + lr[warp] / sum;   // residual: h*attn + h
            float4 hv = *(float4*)(hs + t * 4);      // t*4 lies in row `warp`
            hv.x *= s; hv.y *= s; hv.z *= s; hv.w *= s;
            *(float4*)(hs + t * 4) = hv;
        }
        __syncthreads();

        // ---- stage d: Wh[warp][lane*4 .. +3] = wh[warp,:] @ W ----
        {
            float4 acc = make_float4(0.f, 0.f, 0.f, 0.f);
            const float* whr = hs + warp * FF;
            #pragma unroll 8
            for (int f = 0; f < FF; ++f) {
                const float  wv = whr[f];                              // LDS broadcast
                const float4 wr = *(const float4*)(Ws + f * FF + lane * 4); // LDS.128
                acc.x = fmaf(wv, wr.x, acc.x);
                acc.y = fmaf(wv, wr.y, acc.y);
                acc.z = fmaf(wv, wr.z, acc.z);
                acc.w = fmaf(wv, wr.w, acc.w);
            }
            *(float4*)(Whs + warp * FF + lane * 4) = acc;
        }
        __syncthreads();

        // ---- stage e: Wh1[m], Wh2[m] (warp m) ----
        {
            float4 wr = *(const float4*)(Whs + warp * FF + lane * 4);
            float4 v1 = *(const float4*)(a1S + lane * 4);
            float4 v2 = *(const float4*)(a2S + lane * 4);
            float p1 = wr.x * v1.x + wr.y * v1.y + wr.z * v1.z + wr.w * v1.w;
            float p2 = wr.x * v2.x + wr.y * v2.y + wr.z * v2.z + wr.w * v2.w;
            #pragma unroll
            for (int d = 16; d; d >>= 1) {
                p1 += __shfl_xor_sync(0xffffffffu, p1, d);
                p2 += __shfl_xor_sync(0xffffffffu, p2, d);
            }
            if (lane == 0) { wh1S[warp] = p1; wh2S[warp] = p2; }
        }
        __syncthreads();

        // ---- stage f: masked edge softmax, row i handled by thread i ----
        if (t < MM) {
            const float w2 = wh2S[t];
            float vals[MM];
            float mx = -3.0e38f;
            #pragma unroll
            for (int j = 0; j < MM; ++j) {
                const float v = (adjS[t * MM + j] > 0.0f) ? (wh1S[j] + w2) : NEGV;
                vals[j] = v;
                mx = fmaxf(mx, v);
            }
            float sum = 0.0f;
            #pragma unroll
            for (int j = 0; j < MM; ++j) { vals[j] = expf(vals[j] - mx); sum += vals[j]; }
            const float inv = 1.0f / sum;
            #pragma unroll
            for (int j = 0; j < MM; ++j) attS[t * MM + j] = vals[j] * inv;
        }
        __syncthreads();

        // ---- stage g: out[b, warp, lane*4..] = relu(att[warp,:] @ Wh) ----
        {
            float4 acc = make_float4(0.f, 0.f, 0.f, 0.f);
            #pragma unroll
            for (int j = 0; j < MM; ++j) {
                const float  av = attS[warp * MM + j];
                const float4 wv = *(const float4*)(Whs + j * FF + lane * 4);
                acc.x = fmaf(av, wv.x, acc.x);
                acc.y = fmaf(av, wv.y, acc.y);
                acc.z = fmaf(av, wv.z, acc.z);
                acc.w = fmaf(av, wv.w, acc.w);
            }
            acc.x = fmaxf(acc.x, 0.0f);
            acc.y = fmaxf(acc.y, 0.0f);
            acc.z = fmaxf(acc.z, 0.0f);
            acc.w = fmaxf(acc.w, 0.0f);
            *((float4*)(out + (size_t)b * (MM * FF)) + t) = acc;
        }
        // no trailing sync needed: next iter's stage-a writes (hs, adjS) are
        // ordered behind the syncs after their last readers (stages d and f),
        // and stage g reads only attS/Whs which are rewritten after later syncs.
    }
}

extern "C" void kernel_launch(void* const* d_in, const int* in_sizes, int n_in,
                              void* d_out, int out_size) {
    const float* h      = (const float*)d_in[0];
    const float* adj    = (const float*)d_in[1];
    const float* W      = (const float*)d_in[2];
    const float* a      = (const float*)d_in[3];
    const float* a_node = (const float*)d_in[4];
    // d_in[5]/d_in[6] are node_att/edge_att flags, fixed to 1 in this dataset.

    const int B = in_sizes[0] / (MM * FF);
    const int grid = (B + NB - 1) / NB;
    const size_t smem_bytes = SMEM_FLOATS * sizeof(float);

    cudaFuncSetAttribute(gat_fused_kernel,
                         cudaFuncAttributeMaxDynamicSharedMemorySize,
                         (int)smem_bytes);
    gat_fused_kernel<<<grid, THREADS, smem_bytes>>>(
        h, adj, W, a, a_node, (float*)d_out, B);
}

// round 4
// speedup vs baseline: 2.3395x; 2.3395x over previous
#include <cuda_runtime.h>

// Fused NodeAttention + single-head GAT. B=65536, M=8, F=128, fp32.
//
// Round-2 design:
//  * warp == batch: one warp computes its entire batch. No __syncthreads in
//    the main loop; all reductions are warp shuffles.
//  * GEMM (wh @ W) uses packed f32x2 FMA. W is stored pair-interleaved in
//    smem: Wp[fp][o] = (W[2fp][o], W[2fp+1][o]) packed in 64 bits, so the
//    broadcast operand (h[m][2fp], h[m][2fp+1]) is a natural LDS.64 and each
//    fma.rn.f32x2 performs 2 FMAs. Crossbar cost: per warp per 2-f step =
//    2x LDS.128 (1KB W pairs) + 8 bcast LDS.64 = 16 cyc serving 8 rows x 2 f,
//    i.e. ~1024 crossbar cyc/batch == f32x2 FMA floor (balanced).
//  * Wh kept in registers (as packed pairs, reduced after the GEMM);
//    attn scale s[m] is applied post-GEMM (linear: (diag(s)h)W = diag(s)(hW)).

#define MM 8
#define FF 128
#define ALPHA 0.2f
#define NEGV  (-9e15f)
#define THREADS 256
#define WPB 8            // warps (=batches) per block pass
#define ITERS 4          // passes per block
#define NBB (WPB * ITERS)

struct SmemLayout {
    unsigned long long Wp[64 * FF];   // [fp][o]: (W[2fp][o], W[2fp+1][o])
    float hs[WPB][MM * FF];           // per-warp h tile
    float adjS[WPB][MM * MM];         // per-warp adjacency
};

__device__ __forceinline__ void fma2(unsigned long long& d,
                                     unsigned long long a,
                                     unsigned long long b) {
    asm("fma.rn.f32x2 %0, %1, %2, %0;" : "+l"(d) : "l"(a), "l"(b));
}

__device__ __forceinline__ float2 unpack2(unsigned long long v) {
    unsigned int lo, hi;
    asm("mov.b64 {%0, %1}, %2;" : "=r"(lo), "=r"(hi) : "l"(v));
    return make_float2(__uint_as_float(lo), __uint_as_float(hi));
}

__device__ __forceinline__ unsigned long long pack2(float lo, float hi) {
    unsigned long long v;
    asm("mov.b64 %0, {%1, %2};" : "=l"(v)
        : "r"(__float_as_uint(lo)), "r"(__float_as_uint(hi)));
    return v;
}

__global__ __launch_bounds__(THREADS, 2) void gat_fused_kernel(
    const float* __restrict__ h,
    const float* __restrict__ adj,
    const float* __restrict__ W,
    const float* __restrict__ a,
    const float* __restrict__ a_node,
    float* __restrict__ out,
    int B)
{
    extern __shared__ unsigned char smraw[];
    SmemLayout* sm = reinterpret_cast<SmemLayout*>(smraw);

    const int t    = threadIdx.x;
    const int lane = t & 31;
    const int warp = t >> 5;

    // ---- prologue: build pair-interleaved W in smem ----
    for (int p = t; p < 64 * FF; p += THREADS) {
        const int o  = p & (FF - 1);
        const int fp = p >> 7;
        const float w0 = W[(2 * fp)     * FF + o];
        const float w1 = W[(2 * fp + 1) * FF + o];
        sm->Wp[p] = pack2(w0, w1);
    }
    // lane-private attention vectors (each lane owns o/f slice lane*4..+3)
    const float4 an4 = *(const float4*)(a_node + lane * 4);
    const float4 a14 = *(const float4*)(a + lane * 4);
    const float4 a24 = *(const float4*)(a + FF + lane * 4);
    __syncthreads();

    float* hw   = sm->hs[warp];
    float* adjw = sm->adjS[warp];

    for (int it = 0; it < ITERS; ++it) {
        const int b = blockIdx.x * NBB + it * WPB + warp;
        if (b >= B) continue;

        // ---- stage h tile (8x128) + adj (8x8) into warp-private smem ----
        const float* hb = h + (size_t)b * (MM * FF);
        #pragma unroll
        for (int m = 0; m < MM; ++m)
            *(float4*)(hw + m * FF + lane * 4) =
                *(const float4*)(hb + m * FF + lane * 4);
        *(float2*)(adjw + lane * 2) =
            *(const float2*)(adj + (size_t)b * (MM * MM) + lane * 2);
        __syncwarp();

        // ---- node attention: s[m] = 1 + softmax(leaky_relu(h . a_node)) ----
        float s[MM];
        {
            float en[MM];
            #pragma unroll
            for (int m = 0; m < MM; ++m) {
                const float4 hv = *(const float4*)(hw + m * FF + lane * 4);
                en[m] = hv.x * an4.x + hv.y * an4.y + hv.z * an4.z + hv.w * an4.w;
            }
            #pragma unroll
            for (int m = 0; m < MM; ++m) {
                #pragma unroll
                for (int d = 16; d; d >>= 1)
                    en[m] += __shfl_xor_sync(0xffffffffu, en[m], d);
            }
            float mx = -3.0e38f;
            #pragma unroll
            for (int m = 0; m < MM; ++m) {
                en[m] = (en[m] > 0.0f) ? en[m] : ALPHA * en[m];
                mx = fmaxf(mx, en[m]);
            }
            float sum = 0.0f;
            #pragma unroll
            for (int m = 0; m < MM; ++m) { en[m] = __expf(en[m] - mx); sum += en[m]; }
            const float inv = 1.0f / sum;
            #pragma unroll
            for (int m = 0; m < MM; ++m) s[m] = 1.0f + en[m] * inv;
        }

        // ---- GEMM: Wh[m][o] = sum_f h[m][f] * W[f][o]  (packed f32x2) ----
        // acc[m][k] holds the pair (even-f partial, odd-f partial) for output
        // o = lane*4 + k.
        unsigned long long acc[MM][4];
        #pragma unroll
        for (int m = 0; m < MM; ++m)
            #pragma unroll
            for (int k = 0; k < 4; ++k) acc[m][k] = 0ull;

        {
            const unsigned long long* wrow = sm->Wp + lane * 4;
            #pragma unroll 4
            for (int fp = 0; fp < 64; ++fp) {
                const ulonglong2 wA = *(const ulonglong2*)(wrow + fp * FF);
                const ulonglong2 wB = *(const ulonglong2*)(wrow + fp * FF + 2);
                #pragma unroll
                for (int m = 0; m < MM; ++m) {
                    const unsigned long long h2 =
                        *(const unsigned long long*)(hw + m * FF + 2 * fp);
                    fma2(acc[m][0], wA.x, h2);
                    fma2(acc[m][1], wA.y, h2);
                    fma2(acc[m][2], wB.x, h2);
                    fma2(acc[m][3], wB.y, h2);
                }
            }
        }

        // ---- reduce pairs + apply node-attention scale ----
        float Wh[MM][4];
        #pragma unroll
        for (int m = 0; m < MM; ++m) {
            #pragma unroll
            for (int k = 0; k < 4; ++k) {
                const float2 p = unpack2(acc[m][k]);
                Wh[m][k] = s[m] * (p.x + p.y);
            }
        }

        // ---- Wh1[m] = Wh[m,:].a1 ; Wh2[m] = Wh[m,:].a2 (warp reductions) ----
        float w1r[MM], w2r[MM];
        #pragma unroll
        for (int m = 0; m < MM; ++m) {
            w1r[m] = Wh[m][0] * a14.x + Wh[m][1] * a14.y +
                     Wh[m][2] * a14.z + Wh[m][3] * a14.w;
            w2r[m] = Wh[m][0] * a24.x + Wh[m][1] * a24.y +
                     Wh[m][2] * a24.z + Wh[m][3] * a24.w;
        }
        #pragma unroll
        for (int m = 0; m < MM; ++m) {
            #pragma unroll
            for (int d = 16; d; d >>= 1) {
                w1r[m] += __shfl_xor_sync(0xffffffffu, w1r[m], d);
                w2r[m] += __shfl_xor_sync(0xffffffffu, w2r[m], d);
            }
        }

        // ---- masked edge softmax + out row i = relu(att[i,:] @ Wh) ----
        float* ob = out + (size_t)b * (MM * FF);
        #pragma unroll
        for (int i = 0; i < MM; ++i) {
            float v[MM];
            float mx = -3.0e38f;
            #pragma unroll
            for (int j = 0; j < MM; ++j) {
                const float e = (adjw[i * MM + j] > 0.0f) ? (w1r[j] + w2r[i]) : NEGV;
                v[j] = e;
                mx = fmaxf(mx, e);
            }
            float sum = 0.0f;
            #pragma unroll
            for (int j = 0; j < MM; ++j) { v[j] = __expf(v[j] - mx); sum += v[j]; }
            const float inv = 1.0f / sum;

            float o0 = 0.f, o1 = 0.f, o2 = 0.f, o3 = 0.f;
            #pragma unroll
            for (int j = 0; j < MM; ++j) {
                o0 = fmaf(v[j], Wh[j][0], o0);
                o1 = fmaf(v[j], Wh[j][1], o1);
                o2 = fmaf(v[j], Wh[j][2], o2);
                o3 = fmaf(v[j], Wh[j][3], o3);
            }
            float4 r;
            r.x = fmaxf(o0 * inv, 0.0f);
            r.y = fmaxf(o1 * inv, 0.0f);
            r.z = fmaxf(o2 * inv, 0.0f);
            r.w = fmaxf(o3 * inv, 0.0f);
            *(float4*)(ob + i * FF + lane * 4) = r;
        }
    }
}

extern "C" void kernel_launch(void* const* d_in, const int* in_sizes, int n_in,
                              void* d_out, int out_size) {
    const float* h      = (const float*)d_in[0];
    const float* adj    = (const float*)d_in[1];
    const float* W      = (const float*)d_in[2];
    const float* a      = (const float*)d_in[3];
    const float* a_node = (const float*)d_in[4];

    const int B = in_sizes[0] / (MM * FF);
    const int grid = (B + NBB - 1) / NBB;
    const size_t smem_bytes = sizeof(SmemLayout);

    cudaFuncSetAttribute(gat_fused_kernel,
                         cudaFuncAttributeMaxDynamicSharedMemorySize,
                         (int)smem_bytes);
    gat_fused_kernel<<<grid, THREADS, smem_bytes>>>(
        h, adj, W, a, a_node, (float*)d_out, B);
}

// round 14
// speedup vs baseline: 3.5985x; 1.5381x over previous
#include <cuda_runtime.h>
#include <cuda_bf16.h>
#include <cstdint>

// Fused NodeAttention + GAT, warp-level bf16 mma.sync (m16n8k16, sm_80+ ISA,
// tensor pipe). B=65536, M=8, F=128, fp32 in/out.
//
//  * fp32 fidelity: hi/lo bf16 split, D ~= Ahi*Bhi + Ahi*Blo + Alo*Bhi
//    (error ~1e-5 << 1e-3 tolerance). 3 accumulator sets break the MMA
//    dependency chain.
//  * 16 batches per pass => 128x128x128 GEMM tile. Warp w owns tile rows
//    [16w,16w+16) == its own 2 batches, so h rows, adj, node softmax, Wh rows,
//    E1 and the epilogue are ALL warp-private: no __syncthreads in the main
//    loop, warps pipeline independently.
//  * Edge softmax: e[i,j]=Wh1[j]+Wh2[i]; row term cancels in softmax_j =>
//    att[i,j] = m_ij*exp(Wh1[j])/sum (all-masked row -> uniform, matching
//    reference where(adj>0, e, -9e15)).
//  * Bank-conflict-free fragment feeds: W pair-interleaved (b-frag pair along
//    k is one 32-bit LDS), Wp stride 136 words, A-tile stride 152 halves.

#define MM 8
#define FF 128
#define ALPHA 0.2f
#define THREADS 256
#define NB 16
#define PASSES 8

#define A_STRIDE_B 304   // bytes per A-tile row (152 bf16)
#define WP_STRIDE  136   // uint32 words per Wp row
#define WH_STRIDE  132   // floats per WhS row

// smem byte offsets
#define OFF_AHI    0                         // 128*304 = 38912
#define OFF_ALO    38912                     // 38912
#define OFF_WPHI   77824                     // 64*136*4 = 34816
#define OFF_WPLO   112640                    // 34816
#define OFF_WHS    147456                    // 128*132*4 = 67584
#define OFF_ADJ    215040                    // 16*64*4 = 4096
#define OFF_A1     219136                    // 512
#define OFF_AN     219648                    // 512
#define OFF_ENP    220160                    // 256*4 = 1024
#define OFF_S      221184                    // 512
#define OFF_E1     221696                    // 512
#define SMEM_TOTAL 222208

static __device__ __forceinline__ void mma_bf16(
    float& c0, float& c1, float& c2, float& c3,
    uint32_t a0, uint32_t a1, uint32_t a2, uint32_t a3,
    uint32_t b0, uint32_t b1)
{
    asm volatile(
        "mma.sync.aligned.m16n8k16.row.col.f32.bf16.bf16.f32 "
        "{%0,%1,%2,%3}, {%4,%5,%6,%7}, {%8,%9}, {%0,%1,%2,%3};"
        : "+f"(c0), "+f"(c1), "+f"(c2), "+f"(c3)
        : "r"(a0), "r"(a1), "r"(a2), "r"(a3), "r"(b0), "r"(b1));
}

__global__ __launch_bounds__(THREADS) void gat_mma_kernel(
    const float* __restrict__ h,
    const float* __restrict__ adj,
    const float* __restrict__ W,
    const float* __restrict__ a,
    const float* __restrict__ a_node,
    float* __restrict__ out, int B)
{
    extern __shared__ unsigned char smem[];
    float* WhS  = (float*)(smem + OFF_WHS);
    float* adjS = (float*)(smem + OFF_ADJ);
    float* a1S  = (float*)(smem + OFF_A1);
    float* anS  = (float*)(smem + OFF_AN);
    float* enP  = (float*)(smem + OFF_ENP);
    float* sS   = (float*)(smem + OFF_S);
    float* E1S  = (float*)(smem + OFF_E1);
    uint32_t* WpHi = (uint32_t*)(smem + OFF_WPHI);
    uint32_t* WpLo = (uint32_t*)(smem + OFF_WPLO);

    const int t    = threadIdx.x;
    const int lane = t & 31;
    const int wid  = t >> 5;
    const int r0   = wid * 16;       // warp's tile-row base
    const int gr   = lane >> 2;      // mma groupID
    const int tc   = lane & 3;       // mma threadID-in-group

    // ---- prologue: pair-interleaved bf16 hi/lo W; a_node, a1 ----
    for (int idx = t; idx < 64 * FF; idx += THREADS) {
        const int fp = idx >> 7;
        const int o  = idx & 127;
        const float w0 = W[(2 * fp)     * FF + o];
        const float w1 = W[(2 * fp + 1) * FF + o];
        uint32_t hp, lp;
        asm("cvt.rn.bf16x2.f32 %0, %1, %2;" : "=r"(hp) : "f"(w1), "f"(w0));
        const float l0 = w0 - __uint_as_float(hp << 16);
        const float l1 = w1 - __uint_as_float(hp & 0xffff0000u);
        asm("cvt.rn.bf16x2.f32 %0, %1, %2;" : "=r"(lp) : "f"(l1), "f"(l0));
        WpHi[fp * WP_STRIDE + o] = hp;
        WpLo[fp * WP_STRIDE + o] = lp;
    }
    if (t < FF) { anS[t] = a_node[t]; a1S[t] = a[t]; }
    __syncthreads();

    for (int p = 0; p < PASSES; ++p) {
        const int b0 = (blockIdx.x * PASSES + p) * NB;

        // ---- load: h rows (own 16), bf16 hi/lo split, e_n partials, adj ----
        {
            const int rloc = r0 + (lane >> 1);
            const int half = lane & 1;
            const int c0   = half * 64;
            long grow = (long)b0 * MM + rloc;
            const long gmax = (long)B * MM - 1;
            if (grow > gmax) grow = gmax;
            const float* hb = h + grow * FF + c0;
            float ep = 0.f;
            #pragma unroll
            for (int v = 0; v < 16; ++v) {
                const float4 x  = *(const float4*)(hb + v * 4);
                const float4 av = *(const float4*)(anS + c0 + v * 4);
                ep += x.x * av.x + x.y * av.y + x.z * av.z + x.w * av.w;
                uint32_t hi01, hi23, lo01, lo23;
                asm("cvt.rn.bf16x2.f32 %0, %1, %2;" : "=r"(hi01) : "f"(x.y), "f"(x.x));
                asm("cvt.rn.bf16x2.f32 %0, %1, %2;" : "=r"(hi23) : "f"(x.w), "f"(x.z));
                const float l0 = x.x - __uint_as_float(hi01 << 16);
                const float l1 = x.y - __uint_as_float(hi01 & 0xffff0000u);
                const float l2 = x.z - __uint_as_float(hi23 << 16);
                const float l3 = x.w - __uint_as_float(hi23 & 0xffff0000u);
                asm("cvt.rn.bf16x2.f32 %0, %1, %2;" : "=r"(lo01) : "f"(l1), "f"(l0));
                asm("cvt.rn.bf16x2.f32 %0, %1, %2;" : "=r"(lo23) : "f"(l3), "f"(l2));
                const int off = rloc * A_STRIDE_B + (c0 + v * 4) * 2;
                *(uint2*)(smem + OFF_AHI + off) = make_uint2(hi01, hi23);
                *(uint2*)(smem + OFF_ALO + off) = make_uint2(lo01, lo23);
            }
            enP[rloc * 2 + half] = ep;

            long ab = (long)b0 * (MM * MM) + wid * 128 + lane * 4;
            const long amax = (long)B * (MM * MM) - 4;
            if (ab > amax) ab = amax;
            *(float4*)(adjS + wid * 128 + lane * 4) = *(const float4*)(adj + ab);
        }
        __syncwarp();

        // ---- node softmax for own 2 batches (groups of 8 lanes) ----
        {
            const int gl  = lane & 15;
            const int row = r0 + gl;
            float v = enP[2 * row] + enP[2 * row + 1];
            v = (v > 0.f) ? v : ALPHA * v;
            float mx = v;
            #pragma unroll
            for (int d = 1; d < 8; d <<= 1)
                mx = fmaxf(mx, __shfl_xor_sync(0xffffffffu, mx, d));
            const float e = __expf(v - mx);
            float se = e;
            #pragma unroll
            for (int d = 1; d < 8; d <<= 1)
                se += __shfl_xor_sync(0xffffffffu, se, d);
            if (lane < 16) sS[row] = 1.f + e / se;
        }
        __syncwarp();

        // ---- GEMM: rows [r0, r0+16) x 128 cols, 3-term bf16 split ----
        {
            uint32_t ahi[8][4], alo[8][4];
            const int abase = (r0 + gr) * A_STRIDE_B + tc * 4;
            #pragma unroll
            for (int kt = 0; kt < 8; ++kt) {
                const int o0 = abase + kt * 32;
                ahi[kt][0] = *(const uint32_t*)(smem + OFF_AHI + o0);
                ahi[kt][1] = *(const uint32_t*)(smem + OFF_AHI + o0 + 8 * A_STRIDE_B);
                ahi[kt][2] = *(const uint32_t*)(smem + OFF_AHI + o0 + 16);
                ahi[kt][3] = *(const uint32_t*)(smem + OFF_AHI + o0 + 8 * A_STRIDE_B + 16);
                alo[kt][0] = *(const uint32_t*)(smem + OFF_ALO + o0);
                alo[kt][1] = *(const uint32_t*)(smem + OFF_ALO + o0 + 8 * A_STRIDE_B);
                alo[kt][2] = *(const uint32_t*)(smem + OFF_ALO + o0 + 16);
                alo[kt][3] = *(const uint32_t*)(smem + OFF_ALO + o0 + 8 * A_STRIDE_B + 16);
            }
            const float sA = sS[r0 + gr];
            const float sB = sS[r0 + gr + 8];
            float wh1a = 0.f, wh1b = 0.f;

            #pragma unroll 4
            for (int nt = 0; nt < 16; ++nt) {
                const int o = nt * 8 + gr;
                float c[3][4];
                #pragma unroll
                for (int m = 0; m < 3; ++m)
                    #pragma unroll
                    for (int k = 0; k < 4; ++k) c[m][k] = 0.f;

                #pragma unroll
                for (int kt = 0; kt < 8; ++kt) {
                    const int i0 = (kt * 8 + tc) * WP_STRIDE + o;
                    const int i1 = (kt * 8 + 4 + tc) * WP_STRIDE + o;
                    const uint32_t bh0 = WpHi[i0], bh1 = WpHi[i1];
                    const uint32_t bl0 = WpLo[i0], bl1 = WpLo[i1];
                    mma_bf16(c[0][0], c[0][1], c[0][2], c[0][3],
                             ahi[kt][0], ahi[kt][1], ahi[kt][2], ahi[kt][3], bh0, bh1);
                    mma_bf16(c[1][0], c[1][1], c[1][2], c[1][3],
                             ahi[kt][0], ahi[kt][1], ahi[kt][2], ahi[kt][3], bl0, bl1);
                    mma_bf16(c[2][0], c[2][1], c[2][2], c[2][3],
                             alo[kt][0], alo[kt][1], alo[kt][2], alo[kt][3], bh0, bh1);
                }
                const float v0 = sA * (c[0][0] + c[1][0] + c[2][0]);
                const float v1 = sA * (c[0][1] + c[1][1] + c[2][1]);
                const float v2 = sB * (c[0][2] + c[1][2] + c[2][2]);
                const float v3 = sB * (c[0][3] + c[1][3] + c[2][3]);
                const int colb = nt * 8 + 2 * tc;
                const int idx0 = (r0 + gr) * WH_STRIDE + colb;
                *(float2*)(WhS + idx0) = make_float2(v0, v1);
                *(float2*)(WhS + idx0 + 8 * WH_STRIDE) = make_float2(v2, v3);
                const float a1v0 = a1S[colb], a1v1 = a1S[colb + 1];
                wh1a = fmaf(v0, a1v0, fmaf(v1, a1v1, wh1a));
                wh1b = fmaf(v2, a1v0, fmaf(v3, a1v1, wh1b));
            }
            wh1a += __shfl_xor_sync(0xffffffffu, wh1a, 1);
            wh1a += __shfl_xor_sync(0xffffffffu, wh1a, 2);
            wh1b += __shfl_xor_sync(0xffffffffu, wh1b, 1);
            wh1b += __shfl_xor_sync(0xffffffffu, wh1b, 2);
            if (tc == 0) {
                E1S[r0 + gr]     = __expf(wh1a);
                E1S[r0 + gr + 8] = __expf(wh1b);
            }
        }
        __syncwarp();

        // ---- epilogue: own 2 batches, exp-free masked softmax + att @ Wh ----
        #pragma unroll
        for (int bb = 0; bb < 2; ++bb) {
            const int bl = wid * 2 + bb;
            const int b  = b0 + bl;
            if (b < B) {
                float4 whj[8];
                #pragma unroll
                for (int j = 0; j < 8; ++j)
                    whj[j] = *(const float4*)(WhS + (bl * MM + j) * WH_STRIDE + lane * 4);
                const float4 e1a = *(const float4*)(E1S + bl * MM);
                const float4 e1b = *(const float4*)(E1S + bl * MM + 4);
                float* ob = out + (size_t)b * (MM * FF);
                #pragma unroll
                for (int i = 0; i < MM; ++i) {
                    const float4 ma = *(const float4*)(adjS + bl * 64 + i * MM);
                    const float4 mb = *(const float4*)(adjS + bl * 64 + i * MM + 4);
                    float w0 = (ma.x > 0.f) ? e1a.x : 0.f;
                    float w1 = (ma.y > 0.f) ? e1a.y : 0.f;
                    float w2 = (ma.z > 0.f) ? e1a.z : 0.f;
                    float w3 = (ma.w > 0.f) ? e1a.w : 0.f;
                    float w4 = (mb.x > 0.f) ? e1b.x : 0.f;
                    float w5 = (mb.y > 0.f) ? e1b.y : 0.f;
                    float w6 = (mb.z > 0.f) ? e1b.z : 0.f;
                    float w7 = (mb.w > 0.f) ? e1b.w : 0.f;
                    float ssum = ((w0 + w1) + (w2 + w3)) + ((w4 + w5) + (w6 + w7));
                    if (ssum == 0.f) {   // fully-masked row -> uniform (ref semantics)
                        w0 = w1 = w2 = w3 = w4 = w5 = w6 = w7 = 1.f;
                        ssum = 8.f;
                    }
                    float ax = w0 * whj[0].x, ay = w0 * whj[0].y,
                          az = w0 * whj[0].z, aw = w0 * whj[0].w;
                    ax = fmaf(w1, whj[1].x, ax); ay = fmaf(w1, whj[1].y, ay);
                    az = fmaf(w1, whj[1].z, az); aw = fmaf(w1, whj[1].w, aw);
                    ax = fmaf(w2, whj[2].x, ax); ay = fmaf(w2, whj[2].y, ay);
                    az = fmaf(w2, whj[2].z, az); aw = fmaf(w2, whj[2].w, aw);
                    ax = fmaf(w3, whj[3].x, ax); ay = fmaf(w3, whj[3].y, ay);
                    az = fmaf(w3, whj[3].z, az); aw = fmaf(w3, whj[3].w, aw);
                    ax = fmaf(w4, whj[4].x, ax); ay = fmaf(w4, whj[4].y, ay);
                    az = fmaf(w4, whj[4].z, az); aw = fmaf(w4, whj[4].w, aw);
                    ax = fmaf(w5, whj[5].x, ax); ay = fmaf(w5, whj[5].y, ay);
                    az = fmaf(w5, whj[5].z, az); aw = fmaf(w5, whj[5].w, aw);
                    ax = fmaf(w6, whj[6].x, ax); ay = fmaf(w6, whj[6].y, ay);
                    az = fmaf(w6, whj[6].z, az); aw = fmaf(w6, whj[6].w, aw);
                    ax = fmaf(w7, whj[7].x, ax); ay = fmaf(w7, whj[7].y, ay);
                    az = fmaf(w7, whj[7].z, az); aw = fmaf(w7, whj[7].w, aw);
                    const float inv = 1.f / ssum;
                    float4 res;
                    res.x = fmaxf(ax * inv, 0.f);
                    res.y = fmaxf(ay * inv, 0.f);
                    res.z = fmaxf(az * inv, 0.f);
                    res.w = fmaxf(aw * inv, 0.f);
                    *(float4*)(ob + i * FF + lane * 4) = res;
                }
            }
        }
        __syncwarp();   // protect warp-private smem before next pass overwrite
    }
}

extern "C" void kernel_launch(void* const* d_in, const int* in_sizes, int n_in,
                              void* d_out, int out_size) {
    const float* h      = (const float*)d_in[0];
    const float* adj    = (const float*)d_in[1];
    const float* W      = (const float*)d_in[2];
    const float* a      = (const float*)d_in[3];
    const float* a_node = (const float*)d_in[4];

    const int B = in_sizes[0] / (MM * FF);
    const int grid = (B + NB * PASSES - 1) / (NB * PASSES);   // 512 for B=65536

    cudaFuncSetAttribute(gat_mma_kernel,
                         cudaFuncAttributeMaxDynamicSharedMemorySize, SMEM_TOTAL);
    gat_mma_kernel<<<grid, THREADS, SMEM_TOTAL>>>(
        h, adj, W, a, a_node, (float*)d_out, B);
}

// round 16
// speedup vs baseline: 4.0900x; 1.1366x over previous
#include <cuda_runtime.h>
#include <cuda_bf16.h>
#include <cstdint>

// Fused NodeAttention + GAT, warp-level bf16 mma.sync (m16n8k16), fp32 io.
// Round-15: 512 threads / 16 warps per CTA (still 1 CTA/SM) by shrinking smem:
//  * per-warp union buffer: A bf16 hi/lo tile (dead after register fragment
//    preload) aliased with the fp32 Wh tile written by the GEMM epilogue.
//  * node softmax / scale / exp(Wh1) distribution via warp shuffles (no smem);
//    adj read directly from global in the epilogue (warp-uniform broadcast).
//  * persistent grid-stride over 32-batch chunks, grid = #SMs.
// Math identical to round-14: 3-term bf16 hi/lo split GEMM (err ~1e-5),
// exp-free masked edge softmax (row term Wh2[i] cancels in softmax_j).

#define MM 8
#define FF 128
#define ALPHA 0.2f
#define THREADS 512
#define CHUNK 32            // batches per chunk = 16 warps x 2

#define WP_STRIDE 136       // uint32 words per Wp row (8*tc+gr banks distinct)
#define A_STRIDE  304       // bytes per A row (76 words; 12*gr+tc distinct)
#define ALO_OFF   4864      // 16 * 304
#define WARPBUF   9728      // max(A hi+lo 9728, Wh 16*528=8448)
#define WH_STRIDE 528       // bytes per Wh row (132 floats)

// smem byte offsets
#define OFF_WPHI   0                 // 64*136*4 = 34816
#define OFF_WPLO   34816             // 34816
#define OFF_BUF    69632             // 16 * 9728 = 155648
#define OFF_A1     225280            // 512
#define OFF_AN     225792            // 512
#define SMEM_TOTAL 226304

static __device__ __forceinline__ void mma_bf16(
    float& c0, float& c1, float& c2, float& c3,
    uint32_t a0, uint32_t a1, uint32_t a2, uint32_t a3,
    uint32_t b0, uint32_t b1)
{
    asm volatile(
        "mma.sync.aligned.m16n8k16.row.col.f32.bf16.bf16.f32 "
        "{%0,%1,%2,%3}, {%4,%5,%6,%7}, {%8,%9}, {%0,%1,%2,%3};"
        : "+f"(c0), "+f"(c1), "+f"(c2), "+f"(c3)
        : "r"(a0), "r"(a1), "r"(a2), "r"(a3), "r"(b0), "r"(b1));
}

__global__ __launch_bounds__(THREADS, 1) void gat_mma_kernel(
    const float* __restrict__ h,
    const float* __restrict__ adj,
    const float* __restrict__ W,
    const float* __restrict__ a,
    const float* __restrict__ a_node,
    float* __restrict__ out, int B)
{
    extern __shared__ unsigned char smem[];
    uint32_t* WpHi = (uint32_t*)(smem + OFF_WPHI);
    uint32_t* WpLo = (uint32_t*)(smem + OFF_WPLO);
    float* a1S = (float*)(smem + OFF_A1);
    float* anS = (float*)(smem + OFF_AN);

    const int t    = threadIdx.x;
    const int lane = t & 31;
    const int wid  = t >> 5;
    const int gr   = lane >> 2;   // mma groupID
    const int tc   = lane & 3;    // mma threadID-in-group
    unsigned char* buf = smem + OFF_BUF + wid * WARPBUF;

    // ---- prologue: pair-interleaved bf16 hi/lo W; a_node, a1 ----
    for (int idx = t; idx < 64 * FF; idx += THREADS) {
        const int fp = idx >> 7;
        const int o  = idx & 127;
        const float w0 = W[(2 * fp)     * FF + o];
        const float w1 = W[(2 * fp + 1) * FF + o];
        uint32_t hp, lp;
        asm("cvt.rn.bf16x2.f32 %0, %1, %2;" : "=r"(hp) : "f"(w1), "f"(w0));
        const float l0 = w0 - __uint_as_float(hp << 16);
        const float l1 = w1 - __uint_as_float(hp & 0xffff0000u);
        asm("cvt.rn.bf16x2.f32 %0, %1, %2;" : "=r"(lp) : "f"(l1), "f"(l0));
        WpHi[fp * WP_STRIDE + o] = hp;
        WpLo[fp * WP_STRIDE + o] = lp;
    }
    if (t < FF) { anS[t] = a_node[t]; a1S[t] = a[t]; }
    __syncthreads();

    const int nch = (B + CHUNK - 1) / CHUNK;

    for (int ch = blockIdx.x; ch < nch; ch += gridDim.x) {
        const int b0 = ch * CHUNK + wid * 2;   // this warp's 2 batches

        // ---- load 16 h rows, bf16 hi/lo split; node softmax via shuffles ----
        float sval;
        {
            const int rloc = lane >> 1;
            const int half = lane & 1;
            const int c0   = half * 64;
            long grow = (long)b0 * MM + rloc;
            const long gmax = (long)B * MM - 1;
            if (grow > gmax) grow = gmax;
            const float* hb = h + grow * FF + c0;
            float ep = 0.f;
            #pragma unroll
            for (int v = 0; v < 16; ++v) {
                const float4 x  = *(const float4*)(hb + v * 4);
                const float4 av = *(const float4*)(anS + c0 + v * 4);
                ep += x.x * av.x + x.y * av.y + x.z * av.z + x.w * av.w;
                uint32_t hi01, hi23, lo01, lo23;
                asm("cvt.rn.bf16x2.f32 %0, %1, %2;" : "=r"(hi01) : "f"(x.y), "f"(x.x));
                asm("cvt.rn.bf16x2.f32 %0, %1, %2;" : "=r"(hi23) : "f"(x.w), "f"(x.z));
                const float l0 = x.x - __uint_as_float(hi01 << 16);
                const float l1 = x.y - __uint_as_float(hi01 & 0xffff0000u);
                const float l2 = x.z - __uint_as_float(hi23 << 16);
                const float l3 = x.w - __uint_as_float(hi23 & 0xffff0000u);
                asm("cvt.rn.bf16x2.f32 %0, %1, %2;" : "=r"(lo01) : "f"(l1), "f"(l0));
                asm("cvt.rn.bf16x2.f32 %0, %1, %2;" : "=r"(lo23) : "f"(l3), "f"(l2));
                const int off = rloc * A_STRIDE + (c0 + v * 4) * 2;
                *(uint2*)(buf + off)           = make_uint2(hi01, hi23);
                *(uint2*)(buf + ALO_OFF + off) = make_uint2(lo01, lo23);
            }
            // row total: lanes (2r, 2r+1) -> both hold row r's dot
            float er = ep + __shfl_xor_sync(0xffffffffu, ep, 1);
            er = (er > 0.f) ? er : ALPHA * er;
            // softmax over the 8 rows of this lane's batch (16-lane group)
            float mx = er;
            #pragma unroll
            for (int d = 2; d < 16; d <<= 1)
                mx = fmaxf(mx, __shfl_xor_sync(0xffffffffu, mx, d));
            const float e = __expf(er - mx);
            float se = e;
            #pragma unroll
            for (int d = 2; d < 16; d <<= 1)
                se += __shfl_xor_sync(0xffffffffu, se, d);
            sval = 1.f + e / se;               // scale for row (lane>>1) of group
        }
        __syncwarp();

        // ---- A fragment preload (A smem dead afterwards) ----
        uint32_t ahi[8][4], alo[8][4];
        {
            const int abase = gr * A_STRIDE + tc * 4;
            #pragma unroll
            for (int kt = 0; kt < 8; ++kt) {
                const int o0 = abase + kt * 32;
                ahi[kt][0] = *(const uint32_t*)(buf + o0);
                ahi[kt][1] = *(const uint32_t*)(buf + o0 + 8 * A_STRIDE);
                ahi[kt][2] = *(const uint32_t*)(buf + o0 + 16);
                ahi[kt][3] = *(const uint32_t*)(buf + o0 + 8 * A_STRIDE + 16);
                alo[kt][0] = *(const uint32_t*)(buf + ALO_OFF + o0);
                alo[kt][1] = *(const uint32_t*)(buf + ALO_OFF + o0 + 8 * A_STRIDE);
                alo[kt][2] = *(const uint32_t*)(buf + ALO_OFF + o0 + 16);
                alo[kt][3] = *(const uint32_t*)(buf + ALO_OFF + o0 + 8 * A_STRIDE + 16);
            }
        }
        const float sA = __shfl_sync(0xffffffffu, sval, 2 * gr);
        const float sB = __shfl_sync(0xffffffffu, sval, 16 + 2 * gr);
        __syncwarp();   // all A reads done -> Wh may overwrite the buffer

        // ---- GEMM: 16 rows x 128 cols, 3-term bf16 split; Wh -> union buf ----
        float wh1a = 0.f, wh1b = 0.f;
        #pragma unroll 4
        for (int nt = 0; nt < 16; ++nt) {
            const int o = nt * 8 + gr;
            float c[3][4];
            #pragma unroll
            for (int m = 0; m < 3; ++m)
                #pragma unroll
                for (int k = 0; k < 4; ++k) c[m][k] = 0.f;

            #pragma unroll
            for (int kt = 0; kt < 8; ++kt) {
                const int i0 = (kt * 8 + tc) * WP_STRIDE + o;
                const int i1 = (kt * 8 + 4 + tc) * WP_STRIDE + o;
                const uint32_t bh0 = WpHi[i0], bh1 = WpHi[i1];
                const uint32_t bl0 = WpLo[i0], bl1 = WpLo[i1];
                mma_bf16(c[0][0], c[0][1], c[0][2], c[0][3],
                         ahi[kt][0], ahi[kt][1], ahi[kt][2], ahi[kt][3], bh0, bh1);
                mma_bf16(c[1][0], c[1][1], c[1][2], c[1][3],
                         ahi[kt][0], ahi[kt][1], ahi[kt][2], ahi[kt][3], bl0, bl1);
                mma_bf16(c[2][0], c[2][1], c[2][2], c[2][3],
                         alo[kt][0], alo[kt][1], alo[kt][2], alo[kt][3], bh0, bh1);
            }
            const float v0 = sA * (c[0][0] + c[1][0] + c[2][0]);
            const float v1 = sA * (c[0][1] + c[1][1] + c[2][1]);
            const float v2 = sB * (c[0][2] + c[1][2] + c[2][2]);
            const float v3 = sB * (c[0][3] + c[1][3] + c[2][3]);
            const int colb = nt * 8 + 2 * tc;
            *(float2*)(buf + gr * WH_STRIDE + colb * 4)       = make_float2(v0, v1);
            *(float2*)(buf + (gr + 8) * WH_STRIDE + colb * 4) = make_float2(v2, v3);
            const float a1v0 = a1S[colb], a1v1 = a1S[colb + 1];
            wh1a = fmaf(v0, a1v0, fmaf(v1, a1v1, wh1a));
            wh1b = fmaf(v2, a1v0, fmaf(v3, a1v1, wh1b));
        }
        wh1a += __shfl_xor_sync(0xffffffffu, wh1a, 1);
        wh1a += __shfl_xor_sync(0xffffffffu, wh1a, 2);
        wh1b += __shfl_xor_sync(0xffffffffu, wh1b, 1);
        wh1b += __shfl_xor_sync(0xffffffffu, wh1b, 2);
        const float e1a = __expf(wh1a);   // batch0, row gr (uniform in quad)
        const float e1b = __expf(wh1b);   // batch1, row gr
        __syncwarp();

        // ---- epilogue: 2 batches, exp-free masked softmax + att @ Wh ----
        #pragma unroll
        for (int bb = 0; bb < 2; ++bb) {
            const int b = b0 + bb;
            if (b < B) {
                const float esrc = bb ? e1b : e1a;
                float e1v[8];
                #pragma unroll
                for (int j = 0; j < 8; ++j)
                    e1v[j] = __shfl_sync(0xffffffffu, esrc, 4 * j);
                float4 whj[8];
                #pragma unroll
                for (int j = 0; j < 8; ++j)
                    whj[j] = *(const float4*)(buf + (bb * 8 + j) * WH_STRIDE + lane * 16);
                const float* arow = adj + (size_t)b * (MM * MM);
                float* ob = out + (size_t)b * (MM * FF);
                #pragma unroll
                for (int i = 0; i < MM; ++i) {
                    const float4 ma = *(const float4*)(arow + i * MM);
                    const float4 mb = *(const float4*)(arow + i * MM + 4);
                    float w0 = (ma.x > 0.f) ? e1v[0] : 0.f;
                    float w1 = (ma.y > 0.f) ? e1v[1] : 0.f;
                    float w2 = (ma.z > 0.f) ? e1v[2] : 0.f;
                    float w3 = (ma.w > 0.f) ? e1v[3] : 0.f;
                    float w4 = (mb.x > 0.f) ? e1v[4] : 0.f;
                    float w5 = (mb.y > 0.f) ? e1v[5] : 0.f;
                    float w6 = (mb.z > 0.f) ? e1v[6] : 0.f;
                    float w7 = (mb.w > 0.f) ? e1v[7] : 0.f;
                    float ssum = ((w0 + w1) + (w2 + w3)) + ((w4 + w5) + (w6 + w7));
                    if (ssum == 0.f) {   // fully-masked row -> uniform (ref semantics)
                        w0 = w1 = w2 = w3 = w4 = w5 = w6 = w7 = 1.f;
                        ssum = 8.f;
                    }
                    float ax = w0 * whj[0].x, ay = w0 * whj[0].y,
                          az = w0 * whj[0].z, aw = w0 * whj[0].w;
                    ax = fmaf(w1, whj[1].x, ax); ay = fmaf(w1, whj[1].y, ay);
                    az = fmaf(w1, whj[1].z, az); aw = fmaf(w1, whj[1].w, aw);
                    ax = fmaf(w2, whj[2].x, ax); ay = fmaf(w2, whj[2].y, ay);
                    az = fmaf(w2, whj[2].z, az); aw = fmaf(w2, whj[2].w, aw);
                    ax = fmaf(w3, whj[3].x, ax); ay = fmaf(w3, whj[3].y, ay);
                    az = fmaf(w3, whj[3].z, az); aw = fmaf(w3, whj[3].w, aw);
                    ax = fmaf(w4, whj[4].x, ax); ay = fmaf(w4, whj[4].y, ay);
                    az = fmaf(w4, whj[4].z, az); aw = fmaf(w4, whj[4].w, aw);
                    ax = fmaf(w5, whj[5].x, ax); ay = fmaf(w5, whj[5].y, ay);
                    az = fmaf(w5, whj[5].z, az); aw = fmaf(w5, whj[5].w, aw);
                    ax = fmaf(w6, whj[6].x, ax); ay = fmaf(w6, whj[6].y, ay);
                    az = fmaf(w6, whj[6].z, az); aw = fmaf(w6, whj[6].w, aw);
                    ax = fmaf(w7, whj[7].x, ax); ay = fmaf(w7, whj[7].y, ay);
                    az = fmaf(w7, whj[7].z, az); aw = fmaf(w7, whj[7].w, aw);
                    const float inv = 1.f / ssum;
                    float4 res;
                    res.x = fmaxf(ax * inv, 0.f);
                    res.y = fmaxf(ay * inv, 0.f);
                    res.z = fmaxf(az * inv, 0.f);
                    res.w = fmaxf(aw * inv, 0.f);
                    *(float4*)(ob + i * FF + lane * 4) = res;
                }
            }
        }
        __syncwarp();   // protect union buffer before next chunk's overwrite
    }
}

extern "C" void kernel_launch(void* const* d_in, const int* in_sizes, int n_in,
                              void* d_out, int out_size) {
    const float* h      = (const float*)d_in[0];
    const float* adj    = (const float*)d_in[1];
    const float* W      = (const float*)d_in[2];
    const float* a      = (const float*)d_in[3];
    const float* a_node = (const float*)d_in[4];

    const int B = in_sizes[0] / (MM * FF);
    const int nch = (B + CHUNK - 1) / CHUNK;
    const int grid = (nch < 148) ? nch : 148;   // persistent, 1 CTA/SM

    cudaFuncSetAttribute(gat_mma_kernel,
                         cudaFuncAttributeMaxDynamicSharedMemorySize, SMEM_TOTAL);
    gat_mma_kernel<<<grid, THREADS, SMEM_TOTAL>>>(
        h, adj, W, a, a_node, (float*)d_out, B);
}

// round 17
// speedup vs baseline: 4.6163x; 1.1287x over previous
#include <cuda_runtime.h>
#include <cuda_bf16.h>
#include <cstdint>

// Fused NodeAttention + GAT, warp-level bf16 mma.sync (m16n8k16), fp32 io.
// Round-17:
//  * B-fragment feed via permuted-pair layout: Wq[o][kt*8+perm] puts the two
//    fragment words a lane needs (pair tc and pair tc+4 of each k-tile) in
//    adjacent words -> 1 LDS.64 instead of 2 LDS.32 (512 -> 256 LDS).
//    Row stride 72 words => perfect bank permutation per half-warp.
//  * Epilogue att@Wh moved to the tensor pipe: out(16x128) = P @ Wh with
//    P = blockdiag(att_b0, att_b1) built exactly per lane, 3-term bf16 hi/lo
//    split (P_hi*V_hi + P_hi*V_lo + P_lo*V_hi), V converted on-the-fly from
//    the fp32 WhS tile. Replaces ~860 scalar issues/lane with ~440.
// Math otherwise identical to round-16 (rel_err 4.6e-6): 3-term split GEMM,
// exp-free masked edge softmax (row term Wh2[i] cancels in softmax_j),
// all-masked row -> uniform.

#define MM 8
#define FF 128
#define ALPHA 0.2f
#define THREADS 512
#define CHUNK 32            // batches per chunk = 16 warps x 2

#define WQ_STRIDE 72        // uint32 words per Wq row (perm layout, bank-perfect)
#define A_STRIDE  304       // bytes per A row (152 bf16)
#define ALO_OFF   4864      // 16 * 304
#define WARPBUF   9728      // max(A hi+lo 9728, Wh 16*528=8448)
#define WH_STRIDE 528       // bytes per WhS row (132 floats)

// smem byte offsets
#define OFF_WQHI   0                 // 128*72*4 = 36864
#define OFF_WQLO   36864             // 36864
#define OFF_BUF    73728             // 16 * 9728 = 155648
#define OFF_A1     229376            // 512
#define OFF_AN     229888            // 512
#define SMEM_TOTAL 230400

static __device__ __forceinline__ void mma_bf16(
    float& c0, float& c1, float& c2, float& c3,
    uint32_t a0, uint32_t a1, uint32_t a2, uint32_t a3,
    uint32_t b0, uint32_t b1)
{
    asm volatile(
        "mma.sync.aligned.m16n8k16.row.col.f32.bf16.bf16.f32 "
        "{%0,%1,%2,%3}, {%4,%5,%6,%7}, {%8,%9}, {%0,%1,%2,%3};"
        : "+f"(c0), "+f"(c1), "+f"(c2), "+f"(c3)
        : "r"(a0), "r"(a1), "r"(a2), "r"(a3), "r"(b0), "r"(b1));
}

static __device__ __forceinline__ float bf_lo(uint32_t u) {
    return __uint_as_float(u << 16);
}
static __device__ __forceinline__ float bf_hi(uint32_t u) {
    return __uint_as_float(u & 0xffff0000u);
}

__global__ __launch_bounds__(THREADS, 1) void gat_mma_kernel(
    const float* __restrict__ h,
    const float* __restrict__ adj,
    const float* __restrict__ W,
    const float* __restrict__ a,
    const float* __restrict__ a_node,
    float* __restrict__ out, int B)
{
    extern __shared__ unsigned char smem[];
    uint32_t* WqHi = (uint32_t*)(smem + OFF_WQHI);
    uint32_t* WqLo = (uint32_t*)(smem + OFF_WQLO);
    float* a1S = (float*)(smem + OFF_A1);
    float* anS = (float*)(smem + OFF_AN);

    const int t    = threadIdx.x;
    const int lane = t & 31;
    const int wid  = t >> 5;
    const int gr   = lane >> 2;   // mma groupID
    const int tc   = lane & 3;    // mma threadID-in-group
    unsigned char* buf = smem + OFF_BUF + wid * WARPBUF;

    // ---- prologue: permuted-pair bf16 hi/lo W ----
    // Wq[o][kt*8 + 2j]   = pair fp = kt*8 + j      (j = 0..3)  -> b0 word
    // Wq[o][kt*8 + 2j+1] = pair fp = kt*8 + 4 + j              -> b1 word
    for (int idx = t; idx < FF * 64; idx += THREADS) {
        const int o   = idx >> 6;
        const int pos = idx & 63;
        const int q   = pos & 7;
        const int j   = (q & 1) ? (4 + (q >> 1)) : (q >> 1);
        const int fp  = (pos & ~7) + j;
        const float w0 = W[(2 * fp)     * FF + o];
        const float w1 = W[(2 * fp + 1) * FF + o];
        uint32_t hp, lp;
        asm("cvt.rn.bf16x2.f32 %0, %1, %2;" : "=r"(hp) : "f"(w1), "f"(w0));
        const float l0 = w0 - bf_lo(hp);
        const float l1 = w1 - bf_hi(hp);
        asm("cvt.rn.bf16x2.f32 %0, %1, %2;" : "=r"(lp) : "f"(l1), "f"(l0));
        WqHi[o * WQ_STRIDE + pos] = hp;
        WqLo[o * WQ_STRIDE + pos] = lp;
    }
    if (t < FF) { anS[t] = a_node[t]; a1S[t] = a[t]; }
    __syncthreads();

    const int nch = (B + CHUNK - 1) / CHUNK;

    for (int ch = blockIdx.x; ch < nch; ch += gridDim.x) {
        const int b0 = ch * CHUNK + wid * 2;   // this warp's 2 batches

        // ---- load 16 h rows, bf16 hi/lo split; node softmax via shuffles ----
        float sval;
        {
            const int rloc = lane >> 1;
            const int half = lane & 1;
            const int c0   = half * 64;
            long grow = (long)b0 * MM + rloc;
            const long gmax = (long)B * MM - 1;
            if (grow > gmax) grow = gmax;
            const float* hb = h + grow * FF + c0;
            float ep = 0.f;
            #pragma unroll
            for (int v = 0; v < 16; ++v) {
                const float4 x  = *(const float4*)(hb + v * 4);
                const float4 av = *(const float4*)(anS + c0 + v * 4);
                ep += x.x * av.x + x.y * av.y + x.z * av.z + x.w * av.w;
                uint32_t hi01, hi23, lo01, lo23;
                asm("cvt.rn.bf16x2.f32 %0, %1, %2;" : "=r"(hi01) : "f"(x.y), "f"(x.x));
                asm("cvt.rn.bf16x2.f32 %0, %1, %2;" : "=r"(hi23) : "f"(x.w), "f"(x.z));
                const float l0 = x.x - bf_lo(hi01);
                const float l1 = x.y - bf_hi(hi01);
                const float l2 = x.z - bf_lo(hi23);
                const float l3 = x.w - bf_hi(hi23);
                asm("cvt.rn.bf16x2.f32 %0, %1, %2;" : "=r"(lo01) : "f"(l1), "f"(l0));
                asm("cvt.rn.bf16x2.f32 %0, %1, %2;" : "=r"(lo23) : "f"(l3), "f"(l2));
                const int off = rloc * A_STRIDE + (c0 + v * 4) * 2;
                *(uint2*)(buf + off)           = make_uint2(hi01, hi23);
                *(uint2*)(buf + ALO_OFF + off) = make_uint2(lo01, lo23);
            }
            // row total: lanes (2r, 2r+1) both hold row r's dot
            float er = ep + __shfl_xor_sync(0xffffffffu, ep, 1);
            er = (er > 0.f) ? er : ALPHA * er;
            float mx = er;
            #pragma unroll
            for (int d = 2; d < 16; d <<= 1)
                mx = fmaxf(mx, __shfl_xor_sync(0xffffffffu, mx, d));
            const float e = __expf(er - mx);
            float se = e;
            #pragma unroll
            for (int d = 2; d < 16; d <<= 1)
                se += __shfl_xor_sync(0xffffffffu, se, d);
            sval = 1.f + e / se;
        }
        __syncwarp();

        // ---- A fragment preload (A smem dead afterwards) ----
        uint32_t ahi[8][4], alo[8][4];
        {
            const int abase = gr * A_STRIDE + tc * 4;
            #pragma unroll
            for (int kt = 0; kt < 8; ++kt) {
                const int o0 = abase + kt * 32;
                ahi[kt][0] = *(const uint32_t*)(buf + o0);
                ahi[kt][1] = *(const uint32_t*)(buf + o0 + 8 * A_STRIDE);
                ahi[kt][2] = *(const uint32_t*)(buf + o0 + 16);
                ahi[kt][3] = *(const uint32_t*)(buf + o0 + 8 * A_STRIDE + 16);
                alo[kt][0] = *(const uint32_t*)(buf + ALO_OFF + o0);
                alo[kt][1] = *(const uint32_t*)(buf + ALO_OFF + o0 + 8 * A_STRIDE);
                alo[kt][2] = *(const uint32_t*)(buf + ALO_OFF + o0 + 16);
                alo[kt][3] = *(const uint32_t*)(buf + ALO_OFF + o0 + 8 * A_STRIDE + 16);
            }
        }
        const float sA = __shfl_sync(0xffffffffu, sval, 2 * gr);
        const float sB = __shfl_sync(0xffffffffu, sval, 16 + 2 * gr);
        __syncwarp();   // all A reads done -> Wh may overwrite the buffer

        // ---- GEMM: 16 rows x 128 cols, 3-term bf16 split; Wh -> union buf ----
        float wh1a = 0.f, wh1b = 0.f;
        #pragma unroll 4
        for (int nt = 0; nt < 16; ++nt) {
            const uint32_t* rHi = WqHi + (nt * 8 + gr) * WQ_STRIDE + 2 * tc;
            const uint32_t* rLo = WqLo + (nt * 8 + gr) * WQ_STRIDE + 2 * tc;
            float c[3][4];
            #pragma unroll
            for (int m = 0; m < 3; ++m)
                #pragma unroll
                for (int k = 0; k < 4; ++k) c[m][k] = 0.f;

            #pragma unroll
            for (int kt = 0; kt < 8; ++kt) {
                const uint2 bh = *(const uint2*)(rHi + kt * 8);  // (b0,b1) hi
                const uint2 bl = *(const uint2*)(rLo + kt * 8);  // (b0,b1) lo
                mma_bf16(c[0][0], c[0][1], c[0][2], c[0][3],
                         ahi[kt][0], ahi[kt][1], ahi[kt][2], ahi[kt][3], bh.x, bh.y);
                mma_bf16(c[1][0], c[1][1], c[1][2], c[1][3],
                         ahi[kt][0], ahi[kt][1], ahi[kt][2], ahi[kt][3], bl.x, bl.y);
                mma_bf16(c[2][0], c[2][1], c[2][2], c[2][3],
                         alo[kt][0], alo[kt][1], alo[kt][2], alo[kt][3], bh.x, bh.y);
            }
            const float v0 = sA * (c[0][0] + c[1][0] + c[2][0]);
            const float v1 = sA * (c[0][1] + c[1][1] + c[2][1]);
            const float v2 = sB * (c[0][2] + c[1][2] + c[2][2]);
            const float v3 = sB * (c[0][3] + c[1][3] + c[2][3]);
            const int colb = nt * 8 + 2 * tc;
            *(float2*)(buf + gr * WH_STRIDE + colb * 4)       = make_float2(v0, v1);
            *(float2*)(buf + (gr + 8) * WH_STRIDE + colb * 4) = make_float2(v2, v3);
            const float a1v0 = a1S[colb], a1v1 = a1S[colb + 1];
            wh1a = fmaf(v0, a1v0, fmaf(v1, a1v1, wh1a));
            wh1b = fmaf(v2, a1v0, fmaf(v3, a1v1, wh1b));
        }
        wh1a += __shfl_xor_sync(0xffffffffu, wh1a, 1);
        wh1a += __shfl_xor_sync(0xffffffffu, wh1a, 2);
        wh1b += __shfl_xor_sync(0xffffffffu, wh1b, 1);
        wh1b += __shfl_xor_sync(0xffffffffu, wh1b, 2);
        const float e1a = __expf(wh1a);   // batch0, row gr
        const float e1b = __expf(wh1b);   // batch1, row gr
        __syncwarp();                     // Wh writes visible warp-wide

        // ---- epilogue on tensor pipe: out = blockdiag(att0,att1) @ Wh ----
        {
            const unsigned fm = 0xffffffffu;
            // e1[j] for this lane's P columns j = 2tc, 2tc+1
            const float ej0a = __shfl_sync(fm, e1a, 8 * tc);      // gr = 2tc
            const float ej1a = __shfl_sync(fm, e1a, 8 * tc + 4);  // gr = 2tc+1
            const float ej0b = __shfl_sync(fm, e1b, 8 * tc);
            const float ej1b = __shfl_sync(fm, e1b, 8 * tc + 4);

            long ar0 = (long)((b0     < B) ? b0     : B - 1) * 64 + gr * 8 + 2 * tc;
            long ar1 = (long)((b0 + 1 < B) ? b0 + 1 : B - 1) * 64 + gr * 8 + 2 * tc;
            const float2 A0 = *(const float2*)(adj + ar0);
            const float2 A1 = *(const float2*)(adj + ar1);

            // batch0 att row gr, cols 2tc,2tc+1
            float w0 = (A0.x > 0.f) ? ej0a : 0.f;
            float w1 = (A0.y > 0.f) ? ej1a : 0.f;
            float rs0 = w0 + w1;
            rs0 += __shfl_xor_sync(fm, rs0, 1);
            rs0 += __shfl_xor_sync(fm, rs0, 2);
            const bool z0 = (rs0 == 0.f);
            w0 = z0 ? 1.f : w0;
            w1 = z0 ? 1.f : w1;
            const float inv0 = 1.f / (z0 ? 8.f : rs0);
            const float p0 = w0 * inv0, p1 = w1 * inv0;
            uint32_t pah, pal;
            asm("cvt.rn.bf16x2.f32 %0, %1, %2;" : "=r"(pah) : "f"(p1), "f"(p0));
            {
                const float q0 = p0 - bf_lo(pah), q1 = p1 - bf_hi(pah);
                asm("cvt.rn.bf16x2.f32 %0, %1, %2;" : "=r"(pal) : "f"(q1), "f"(q0));
            }
            // batch1
            float u0 = (A1.x > 0.f) ? ej0b : 0.f;
            float u1 = (A1.y > 0.f) ? ej1b : 0.f;
            float rs1 = u0 + u1;
            rs1 += __shfl_xor_sync(fm, rs1, 1);
            rs1 += __shfl_xor_sync(fm, rs1, 2);
            const bool z1 = (rs1 == 0.f);
            u0 = z1 ? 1.f : u0;
            u1 = z1 ? 1.f : u1;
            const float inv1 = 1.f / (z1 ? 8.f : rs1);
            const float s0 = u0 * inv1, s1 = u1 * inv1;
            uint32_t pbh, pbl;
            asm("cvt.rn.bf16x2.f32 %0, %1, %2;" : "=r"(pbh) : "f"(s1), "f"(s0));
            {
                const float q0 = s0 - bf_lo(pbh), q1 = s1 - bf_hi(pbh);
                asm("cvt.rn.bf16x2.f32 %0, %1, %2;" : "=r"(pbl) : "f"(q1), "f"(q0));
            }

            const bool st0 = (b0 < B), st1 = (b0 + 1 < B);
            float* ob0 = out + (size_t)b0 * (MM * FF) + gr * FF;
            float* ob1 = ob0 + MM * FF;

            #pragma unroll
            for (int nt = 0; nt < 16; ++nt) {
                const int cb4 = (nt * 8 + gr) * 4;
                // V fragment: rows {2tc,2tc+1} (b0 block), {2tc+8,2tc+9} (b1)
                const float v0 = *(const float*)(buf + (2 * tc)     * WH_STRIDE + cb4);
                const float v1 = *(const float*)(buf + (2 * tc + 1) * WH_STRIDE + cb4);
                const float v2 = *(const float*)(buf + (2 * tc + 8) * WH_STRIDE + cb4);
                const float v3 = *(const float*)(buf + (2 * tc + 9) * WH_STRIDE + cb4);
                uint32_t bh0, bh1, bl0, bl1;
                asm("cvt.rn.bf16x2.f32 %0, %1, %2;" : "=r"(bh0) : "f"(v1), "f"(v0));
                asm("cvt.rn.bf16x2.f32 %0, %1, %2;" : "=r"(bh1) : "f"(v3), "f"(v2));
                const float r0 = v0 - bf_lo(bh0), r1 = v1 - bf_hi(bh0);
                const float r2 = v2 - bf_lo(bh1), r3 = v3 - bf_hi(bh1);
                asm("cvt.rn.bf16x2.f32 %0, %1, %2;" : "=r"(bl0) : "f"(r1), "f"(r0));
                asm("cvt.rn.bf16x2.f32 %0, %1, %2;" : "=r"(bl1) : "f"(r3), "f"(r2));

                float c0 = 0.f, c1 = 0.f, c2 = 0.f, c3 = 0.f;
                mma_bf16(c0, c1, c2, c3, pah, 0u, 0u, pbh, bh0, bh1);
                mma_bf16(c0, c1, c2, c3, pah, 0u, 0u, pbh, bl0, bl1);
                mma_bf16(c0, c1, c2, c3, pal, 0u, 0u, pbl, bh0, bh1);

                if (st0)
                    *(float2*)(ob0 + nt * 8 + 2 * tc) =
                        make_float2(fmaxf(c0, 0.f), fmaxf(c1, 0.f));
                if (st1)
                    *(float2*)(ob1 + nt * 8 + 2 * tc) =
                        make_float2(fmaxf(c2, 0.f), fmaxf(c3, 0.f));
            }
        }
        __syncwarp();   // protect union buffer before next chunk's overwrite
    }
}

extern "C" void kernel_launch(void* const* d_in, const int* in_sizes, int n_in,
                              void* d_out, int out_size) {
    const float* h      = (const float*)d_in[0];
    const float* adj    = (const float*)d_in[1];
    const float* W      = (const float*)d_in[2];
    const float* a      = (const float*)d_in[3];
    const float* a_node = (const float*)d_in[4];

    const int B = in_sizes[0] / (MM * FF);
    const int nch = (B + CHUNK - 1) / CHUNK;
    const int grid = (nch < 148) ? nch : 148;   // persistent, 1 CTA/SM

    cudaFuncSetAttribute(gat_mma_kernel,
                         cudaFuncAttributeMaxDynamicSharedMemorySize, SMEM_TOTAL);
    gat_mma_kernel<<<grid, THREADS, SMEM_TOTAL>>>(
        h, adj, W, a, a_node, (float*)d_out, B);
}